// round 1
// baseline (speedup 1.0000x reference)
#include <cuda_runtime.h>

// Problem constants
static constexpr int TOK = 2048;   // sequence length
static constexpr int D   = 1024;   // model dim
static constexpr int H3  = 3072;   // 3*D
static constexpr int NH  = 16;     // heads
static constexpr int NOFF = 44;    // number of offsets

__device__ __constant__ int c_offs[NOFF] = {
    0,1,2,3,4,5,6,7,8,9,10,11,12,13,14,15,16,17,18,19,20,21,22,23,24,
    25,26,27,28,29,30,31,32,48,64,96,128,192,256,384,512,768,1024,1536};

// Scratch (allocation-free): qkv [2048,3072], gate [2048,1024], a2 = flat*gate [2048,1024]
__device__ float g_qkv[TOK * H3];
__device__ float g_gate[TOK * D];
__device__ float g_a2[TOK * D];

// ----------------------------------------------------------------------------
// SGEMM: C[M,N] = A[M,K] @ B[N,K]^T + bias[N]   (EPI==1: sigmoid epilogue)
// 128x128 block tile, BK=8, 256 threads, 8x8 per-thread microtile.
// M,N multiples of 128; K multiple of 8 (true for all three GEMMs here).
// ----------------------------------------------------------------------------
template <int EPI>
__global__ __launch_bounds__(256) void sgemm_kernel(
    const float* __restrict__ A, const float* __restrict__ B,
    const float* __restrict__ bias, float* __restrict__ C,
    int N, int K)
{
    __shared__ float As[8][128];
    __shared__ float Bs[8][128];

    const int tid = threadIdx.x;
    const int m0 = blockIdx.y * 128;
    const int n0 = blockIdx.x * 128;

    // loaders: each thread brings one float4 of A and one of B per K-step
    const int lr = tid >> 1;          // 0..127 (row within tile)
    const int lc = (tid & 1) << 2;    // 0 or 4 (col within 8-wide K tile)
    const float* Ap = A + (size_t)(m0 + lr) * K + lc;
    const float* Bp = B + (size_t)(n0 + lr) * K + lc;

    const int tx = tid & 15;          // 0..15
    const int ty = tid >> 4;          // 0..15

    float acc[8][8];
#pragma unroll
    for (int i = 0; i < 8; i++)
#pragma unroll
        for (int j = 0; j < 8; j++) acc[i][j] = 0.f;

    for (int k0 = 0; k0 < K; k0 += 8) {
        float4 av = *(const float4*)(Ap + k0);
        float4 bv = *(const float4*)(Bp + k0);
        As[lc + 0][lr] = av.x; As[lc + 1][lr] = av.y;
        As[lc + 2][lr] = av.z; As[lc + 3][lr] = av.w;
        Bs[lc + 0][lr] = bv.x; Bs[lc + 1][lr] = bv.y;
        Bs[lc + 2][lr] = bv.z; Bs[lc + 3][lr] = bv.w;
        __syncthreads();

#pragma unroll
        for (int kk = 0; kk < 8; kk++) {
            float4 a0 = *(const float4*)&As[kk][ty * 4];
            float4 a1 = *(const float4*)&As[kk][ty * 4 + 64];
            float4 b0 = *(const float4*)&Bs[kk][tx * 4];
            float4 b1 = *(const float4*)&Bs[kk][tx * 4 + 64];
            float ar[8] = {a0.x, a0.y, a0.z, a0.w, a1.x, a1.y, a1.z, a1.w};
            float br[8] = {b0.x, b0.y, b0.z, b0.w, b1.x, b1.y, b1.z, b1.w};
#pragma unroll
            for (int i = 0; i < 8; i++)
#pragma unroll
                for (int j = 0; j < 8; j++)
                    acc[i][j] = fmaf(ar[i], br[j], acc[i][j]);
        }
        __syncthreads();
    }

#pragma unroll
    for (int i = 0; i < 8; i++) {
        int r = m0 + ty * 4 + ((i < 4) ? i : 64 + (i - 4));
#pragma unroll
        for (int jj = 0; jj < 2; jj++) {
            int c = n0 + tx * 4 + jj * 64;
            float4 o;
            o.x = acc[i][jj * 4 + 0] + bias[c + 0];
            o.y = acc[i][jj * 4 + 1] + bias[c + 1];
            o.z = acc[i][jj * 4 + 2] + bias[c + 2];
            o.w = acc[i][jj * 4 + 3] + bias[c + 3];
            if (EPI == 1) {
                o.x = 1.f / (1.f + __expf(-o.x));
                o.y = 1.f / (1.f + __expf(-o.y));
                o.z = 1.f / (1.f + __expf(-o.z));
                o.w = 1.f / (1.f + __expf(-o.w));
            }
            *(float4*)(C + (size_t)r * N + c) = o;
        }
    }
}

// ----------------------------------------------------------------------------
// Attention: one warp per (token n, head h). Lane owns dims {lane, lane+32}.
// scores_o = scale * q . k[n-off_o] + pos_bias[o,h]  (o = 0..43), masked n<off.
// a2[n, h*64+d] = (softmax(scores) . V)[d] * gate[n, h*64+d]
// ----------------------------------------------------------------------------
__global__ __launch_bounds__(256) void attn_kernel(
    const float* __restrict__ qkv, const float* __restrict__ gate,
    const float* __restrict__ pos_bias, float* __restrict__ a2)
{
    const int gwarp = (blockIdx.x * blockDim.x + threadIdx.x) >> 5;
    const int lane  = threadIdx.x & 31;
    const int n = gwarp >> 4;      // token
    const int h = gwarp & 15;      // head
    if (n >= TOK) return;

    const float* qrow = qkv + (size_t)n * H3 + h * 64;
    const float q0 = qrow[lane];
    const float q1 = qrow[lane + 32];

    const float NEG = -1e30f;
    float s0 = NEG, s1 = NEG;   // lane stores score for o=lane (s0) and o=32+lane (s1)

#pragma unroll
    for (int o = 0; o < NOFF; o++) {
        const int off = c_offs[o];
        const int src = n - off;
        float sc = NEG;
        if (src >= 0) {
            const float* krow = qkv + (size_t)src * H3 + D + h * 64;
            float p = q0 * krow[lane] + q1 * krow[lane + 32];
            p += __shfl_xor_sync(0xffffffffu, p, 16);
            p += __shfl_xor_sync(0xffffffffu, p, 8);
            p += __shfl_xor_sync(0xffffffffu, p, 4);
            p += __shfl_xor_sync(0xffffffffu, p, 2);
            p += __shfl_xor_sync(0xffffffffu, p, 1);
            sc = p * 0.125f + pos_bias[o * NH + h];
        }
        if ((o & 31) == lane) {
            if (o < 32) s0 = sc; else s1 = sc;
        }
    }

    // softmax over 44 scores distributed across lanes
    float m = fmaxf(s0, s1);
    m = fmaxf(m, __shfl_xor_sync(0xffffffffu, m, 16));
    m = fmaxf(m, __shfl_xor_sync(0xffffffffu, m, 8));
    m = fmaxf(m, __shfl_xor_sync(0xffffffffu, m, 4));
    m = fmaxf(m, __shfl_xor_sync(0xffffffffu, m, 2));
    m = fmaxf(m, __shfl_xor_sync(0xffffffffu, m, 1));

    float e0 = (s0 > NEG) ? __expf(s0 - m) : 0.f;
    float e1 = (s1 > NEG) ? __expf(s1 - m) : 0.f;

    float sum = e0 + e1;
    sum += __shfl_xor_sync(0xffffffffu, sum, 16);
    sum += __shfl_xor_sync(0xffffffffu, sum, 8);
    sum += __shfl_xor_sync(0xffffffffu, sum, 4);
    sum += __shfl_xor_sync(0xffffffffu, sum, 2);
    sum += __shfl_xor_sync(0xffffffffu, sum, 1);
    const float inv = 1.f / sum;

    float acc0 = 0.f, acc1 = 0.f;
#pragma unroll
    for (int o = 0; o < NOFF; o++) {
        const int off = c_offs[o];
        const int src = n - off;
        if (src >= 0) {
            float ev = (o < 32) ? e0 : e1;
            float al = __shfl_sync(0xffffffffu, ev, o & 31);
            const float* vrow = qkv + (size_t)src * H3 + 2 * D + h * 64;
            acc0 = fmaf(al, vrow[lane], acc0);
            acc1 = fmaf(al, vrow[lane + 32], acc1);
        }
    }
    acc0 *= inv;
    acc1 *= inv;

    const int oi = n * D + h * 64 + lane;
    a2[oi]      = acc0 * gate[oi];
    a2[oi + 32] = acc1 * gate[oi + 32];
}

// ----------------------------------------------------------------------------
// kernel_launch: qkv GEMM -> gate GEMM -> attention (fused gate mult) -> out GEMM
// ----------------------------------------------------------------------------
extern "C" void kernel_launch(void* const* d_in, const int* in_sizes, int n_in,
                              void* d_out, int out_size)
{
    const float* x        = (const float*)d_in[0];
    const float* Wqkv     = (const float*)d_in[1];
    const float* bqkv     = (const float*)d_in[2];
    const float* Wout     = (const float*)d_in[3];
    const float* bout     = (const float*)d_in[4];
    const float* Wgate    = (const float*)d_in[5];
    const float* bgate    = (const float*)d_in[6];
    const float* pos_bias = (const float*)d_in[7];
    float* out = (float*)d_out;

    float *qkv, *gate, *a2;
    cudaGetSymbolAddress((void**)&qkv,  g_qkv);
    cudaGetSymbolAddress((void**)&gate, g_gate);
    cudaGetSymbolAddress((void**)&a2,   g_a2);

    dim3 blk(256);
    // qkv = x @ Wqkv^T + bqkv          [2048, 3072]
    sgemm_kernel<0><<<dim3(H3 / 128, TOK / 128), blk>>>(x, Wqkv, bqkv, qkv, H3, D);
    // gate = sigmoid(x @ Wgate^T + bg) [2048, 1024]
    sgemm_kernel<1><<<dim3(D / 128, TOK / 128), blk>>>(x, Wgate, bgate, gate, D, D);
    // attention + gate multiply -> a2  [2048, 1024]
    attn_kernel<<<(TOK * NH) / 8, 256>>>(qkv, gate, pos_bias, a2);
    // out = a2 @ Wout^T + bout         [2048, 1024]
    sgemm_kernel<0><<<dim3(D / 128, TOK / 128), blk>>>(a2, Wout, bout, out, D, D);
}

// round 3
// speedup vs baseline: 1.9127x; 1.9127x over previous
#include <cuda_runtime.h>
#include <cuda_bf16.h>
#include <cstdint>

// ---------------------------------------------------------------------------
// Problem constants
// ---------------------------------------------------------------------------
static constexpr int TOK = 2048;
static constexpr int D   = 1024;
static constexpr int H3  = 3072;
static constexpr int NH  = 16;
static constexpr int NOFF = 44;

__device__ __constant__ int c_offs[NOFF] = {
    0,1,2,3,4,5,6,7,8,9,10,11,12,13,14,15,16,17,18,19,20,21,22,23,24,
    25,26,27,28,29,30,31,32,48,64,96,128,192,256,384,512,768,1024,1536};

// ---------------------------------------------------------------------------
// Scratch (allocation-free)
// ---------------------------------------------------------------------------
__device__ float g_qkv [TOK * H3];
__device__ float g_gate[TOK * D];
__device__ __nv_bfloat16 g_xh [TOK * D], g_xl [TOK * D];
__device__ __nv_bfloat16 g_wqh[H3 * D], g_wql[H3 * D];
__device__ __nv_bfloat16 g_wgh[D * D],  g_wgl[D * D];
__device__ __nv_bfloat16 g_woh[D * D],  g_wol[D * D];
__device__ __nv_bfloat16 g_a2h[TOK * D], g_a2l[TOK * D];

// ---------------------------------------------------------------------------
// PTX helpers (portable: cp.async / ldmatrix / mma.sync — no 'a' features)
// ---------------------------------------------------------------------------
__device__ __forceinline__ uint32_t smem_u32(const void* p) {
    uint32_t a;
    asm("{ .reg .u64 t; cvta.to.shared.u64 t, %1; cvt.u32.u64 %0, t; }"
        : "=r"(a) : "l"(p));
    return a;
}

#define CP_ASYNC16(dst, src) \
    asm volatile("cp.async.cg.shared.global [%0], [%1], 16;" :: "r"(dst), "l"(src))
#define CP_COMMIT() asm volatile("cp.async.commit_group;" ::: "memory")
#define CP_WAIT1()  asm volatile("cp.async.wait_group 1;"  ::: "memory")

#define LDMX4(r, addr) \
    asm volatile("ldmatrix.sync.aligned.m8n8.x4.shared.b16 {%0,%1,%2,%3}, [%4];" \
                 : "=r"((r)[0]), "=r"((r)[1]), "=r"((r)[2]), "=r"((r)[3]) : "r"(addr))

#define MMA16816(d, a, b0, b1) \
    asm volatile("mma.sync.aligned.m16n8k16.row.col.f32.bf16.bf16.f32 " \
                 "{%0,%1,%2,%3}, {%4,%5,%6,%7}, {%8,%9}, {%0,%1,%2,%3};" \
                 : "+f"((d)[0]), "+f"((d)[1]), "+f"((d)[2]), "+f"((d)[3]) \
                 : "r"((a)[0]), "r"((a)[1]), "r"((a)[2]), "r"((a)[3]), \
                   "r"(b0), "r"(b1))

// ---------------------------------------------------------------------------
// fp32 -> bf16 hi/lo split
// ---------------------------------------------------------------------------
__global__ __launch_bounds__(256) void split_kernel(
    const float4* __restrict__ in, uint2* __restrict__ hi, uint2* __restrict__ lo, int n4)
{
    int i = blockIdx.x * 256 + threadIdx.x;
    if (i >= n4) return;
    float4 a = in[i];
    float av[4] = {a.x, a.y, a.z, a.w};
    uint32_t hh[4], ll[4];
#pragma unroll
    for (int k = 0; k < 4; k++) {
        __nv_bfloat16 h = __float2bfloat16(av[k]);
        float r = av[k] - __bfloat162float(h);
        __nv_bfloat16 l = __float2bfloat16(r);
        hh[k] = (uint32_t)__bfloat16_as_ushort(h);
        ll[k] = (uint32_t)__bfloat16_as_ushort(l);
    }
    uint2 hv, lv;
    hv.x = hh[0] | (hh[1] << 16); hv.y = hh[2] | (hh[3] << 16);
    lv.x = ll[0] | (ll[1] << 16); lv.y = ll[2] | (ll[3] << 16);
    hi[i] = hv; lo[i] = lv;
}

// ---------------------------------------------------------------------------
// HMMA GEMM: C[M,N] = split(A) @ split(B)^T + bias  (EPI==1: sigmoid)
// A:[M,K] bf16 hi/lo, B:[N,K] bf16 hi/lo. 3 virtual K segments.
// CTA tile 128x128, BK=64, 8 warps (warp tile 64x32), double-buffered cp.async.
// ---------------------------------------------------------------------------
template <int EPI>
__global__ __launch_bounds__(256) void hmma_gemm(
    const __nv_bfloat16* __restrict__ Ah, const __nv_bfloat16* __restrict__ Al,
    const __nv_bfloat16* __restrict__ Bh, const __nv_bfloat16* __restrict__ Bl,
    const float* __restrict__ bias, float* __restrict__ C,
    int N, int K)
{
    extern __shared__ char smraw[];
    uint32_t sb = (smem_u32(smraw) + 127u) & ~127u;
    // stage s: A tile at sb + s*32768, B tile at +16384 (each 128 rows x 128B, SW128)

    const int tid  = threadIdx.x;
    const int lane = tid & 31;
    const int wid  = tid >> 5;
    const int wm   = wid & 1;       // 0..1 -> 64-row slab
    const int wn   = wid >> 1;      // 0..3 -> 32-col slab
    const int m0 = blockIdx.y * 128;
    const int n0 = blockIdx.x * 128;

    const __nv_bfloat16* Aseg[3] = {Ah, Al, Ah};
    const __nv_bfloat16* Bseg[3] = {Bh, Bh, Bl};
    const int kc64   = K >> 6;
    const int nchunk = 3 * kc64;

    float acc[4][4][4];
#pragma unroll
    for (int i = 0; i < 4; i++)
#pragma unroll
        for (int j = 0; j < 4; j++)
#pragma unroll
            for (int q = 0; q < 4; q++) acc[i][j][q] = 0.f;

    // ldmatrix per-thread row geometry
    const int a_r  = wm * 64 + ((lane >> 3) & 1) * 8 + (lane & 7);
    const int a_kc = (lane >> 4);            // 0/1: k8 sub-chunk
    const int b_r  = wn * 32 + ((lane >> 4) & 1) * 8 + (lane & 7);
    const int b_kc = ((lane >> 3) & 1);

    // cp.async tile loader: 1024 x 16B per tile (A and B), 4 per thread each
    auto load_tile = [&](int i) {
        const int seg = i / kc64;
        const int kb  = (i - seg * kc64) * 64;
        const int st  = i & 1;
        const uint32_t abase = sb + st * 32768u;
        const uint32_t bbase = abase + 16384u;
        const __nv_bfloat16* Ag = Aseg[seg];
        const __nv_bfloat16* Bg = Bseg[seg];
#pragma unroll
        for (int t = 0; t < 4; t++) {
            int u = tid + t * 256;
            int row = u >> 3, c = u & 7;
            uint32_t dst = abase + (uint32_t)row * 128u + (uint32_t)((c ^ (row & 7)) * 16);
            CP_ASYNC16(dst, (const void*)(Ag + (size_t)(m0 + row) * K + kb + c * 8));
        }
#pragma unroll
        for (int t = 0; t < 4; t++) {
            int u = tid + t * 256;
            int row = u >> 3, c = u & 7;
            uint32_t dst = bbase + (uint32_t)row * 128u + (uint32_t)((c ^ (row & 7)) * 16);
            CP_ASYNC16(dst, (const void*)(Bg + (size_t)(n0 + row) * K + kb + c * 8));
        }
    };

    load_tile(0);
    CP_COMMIT();

    for (int i = 0; i < nchunk; i++) {
        if (i + 1 < nchunk) load_tile(i + 1);
        CP_COMMIT();
        CP_WAIT1();
        __syncthreads();

        const int st = i & 1;
        const uint32_t abase = sb + st * 32768u;
        const uint32_t bbase = abase + 16384u;

#pragma unroll
        for (int ks = 0; ks < 4; ks++) {
            uint32_t afr[4][4], bfr[2][4];
#pragma unroll
            for (int mi = 0; mi < 4; mi++) {
                int r = a_r + mi * 16;
                uint32_t addr = abase + (uint32_t)r * 128u
                              + (uint32_t)((((ks * 2 + a_kc) ^ (r & 7))) * 16);
                LDMX4(afr[mi], addr);
            }
#pragma unroll
            for (int ng = 0; ng < 2; ng++) {
                int r = b_r + ng * 16;
                uint32_t addr = bbase + (uint32_t)r * 128u
                              + (uint32_t)((((ks * 2 + b_kc) ^ (r & 7))) * 16);
                LDMX4(bfr[ng], addr);
            }
#pragma unroll
            for (int mi = 0; mi < 4; mi++)
#pragma unroll
                for (int ni = 0; ni < 4; ni++)
                    MMA16816(acc[mi][ni], afr[mi],
                             bfr[ni >> 1][(ni & 1) * 2], bfr[ni >> 1][(ni & 1) * 2 + 1]);
        }
        __syncthreads();
    }

    // epilogue
    const int mrow = lane >> 2;
    const int ncol = (lane & 3) * 2;
#pragma unroll
    for (int mi = 0; mi < 4; mi++) {
#pragma unroll
        for (int half = 0; half < 2; half++) {
            const int m = m0 + wm * 64 + mi * 16 + mrow + half * 8;
            float* crow = C + (size_t)m * N;
#pragma unroll
            for (int ni = 0; ni < 4; ni++) {
                const int n = n0 + wn * 32 + ni * 8 + ncol;
                float v0 = acc[mi][ni][half * 2 + 0] + bias[n];
                float v1 = acc[mi][ni][half * 2 + 1] + bias[n + 1];
                if (EPI == 1) {
                    v0 = 1.f / (1.f + __expf(-v0));
                    v1 = 1.f / (1.f + __expf(-v1));
                }
                float2 o = {v0, v1};
                *(float2*)(crow + n) = o;
            }
        }
    }
}

// ---------------------------------------------------------------------------
// Attention: one warp per (token, head); fused gate; emits bf16-split a2.
// ---------------------------------------------------------------------------
__global__ __launch_bounds__(256) void attn_kernel(
    const float* __restrict__ qkv, const float* __restrict__ gate,
    const float* __restrict__ pos_bias,
    __nv_bfloat16* __restrict__ a2h, __nv_bfloat16* __restrict__ a2l)
{
    const int gwarp = (blockIdx.x * blockDim.x + threadIdx.x) >> 5;
    const int lane  = threadIdx.x & 31;
    const int n = gwarp >> 4;
    const int h = gwarp & 15;
    if (n >= TOK) return;

    const float* qrow = qkv + (size_t)n * H3 + h * 64;
    const float q0 = qrow[lane];
    const float q1 = qrow[lane + 32];

    const float NEG = -1e30f;
    float s0 = NEG, s1 = NEG;

#pragma unroll
    for (int o = 0; o < NOFF; o++) {
        const int off = c_offs[o];
        const int src = n - off;
        float sc = NEG;
        if (src >= 0) {
            const float* krow = qkv + (size_t)src * H3 + D + h * 64;
            float p = q0 * krow[lane] + q1 * krow[lane + 32];
            p += __shfl_xor_sync(0xffffffffu, p, 16);
            p += __shfl_xor_sync(0xffffffffu, p, 8);
            p += __shfl_xor_sync(0xffffffffu, p, 4);
            p += __shfl_xor_sync(0xffffffffu, p, 2);
            p += __shfl_xor_sync(0xffffffffu, p, 1);
            sc = p * 0.125f + pos_bias[o * NH + h];
        }
        if ((o & 31) == lane) {
            if (o < 32) s0 = sc; else s1 = sc;
        }
    }

    float m = fmaxf(s0, s1);
    m = fmaxf(m, __shfl_xor_sync(0xffffffffu, m, 16));
    m = fmaxf(m, __shfl_xor_sync(0xffffffffu, m, 8));
    m = fmaxf(m, __shfl_xor_sync(0xffffffffu, m, 4));
    m = fmaxf(m, __shfl_xor_sync(0xffffffffu, m, 2));
    m = fmaxf(m, __shfl_xor_sync(0xffffffffu, m, 1));

    float e0 = (s0 > NEG) ? __expf(s0 - m) : 0.f;
    float e1 = (s1 > NEG) ? __expf(s1 - m) : 0.f;

    float sum = e0 + e1;
    sum += __shfl_xor_sync(0xffffffffu, sum, 16);
    sum += __shfl_xor_sync(0xffffffffu, sum, 8);
    sum += __shfl_xor_sync(0xffffffffu, sum, 4);
    sum += __shfl_xor_sync(0xffffffffu, sum, 2);
    sum += __shfl_xor_sync(0xffffffffu, sum, 1);
    const float inv = 1.f / sum;

    float acc0 = 0.f, acc1 = 0.f;
#pragma unroll
    for (int o = 0; o < NOFF; o++) {
        const int off = c_offs[o];
        const int src = n - off;
        if (src >= 0) {
            float ev = (o < 32) ? e0 : e1;
            float al = __shfl_sync(0xffffffffu, ev, o & 31);
            const float* vrow = qkv + (size_t)src * H3 + 2 * D + h * 64;
            acc0 = fmaf(al, vrow[lane], acc0);
            acc1 = fmaf(al, vrow[lane + 32], acc1);
        }
    }
    acc0 *= inv;
    acc1 *= inv;

    const int oi = n * D + h * 64 + lane;
    float v0 = acc0 * gate[oi];
    float v1 = acc1 * gate[oi + 32];

    __nv_bfloat16 h0 = __float2bfloat16(v0);
    __nv_bfloat16 h1 = __float2bfloat16(v1);
    a2h[oi]      = h0;
    a2h[oi + 32] = h1;
    a2l[oi]      = __float2bfloat16(v0 - __bfloat162float(h0));
    a2l[oi + 32] = __float2bfloat16(v1 - __bfloat162float(h1));
}

// ---------------------------------------------------------------------------
// kernel_launch
// ---------------------------------------------------------------------------
extern "C" void kernel_launch(void* const* d_in, const int* in_sizes, int n_in,
                              void* d_out, int out_size)
{
    const float* x        = (const float*)d_in[0];
    const float* Wqkv     = (const float*)d_in[1];
    const float* bqkv     = (const float*)d_in[2];
    const float* Wout     = (const float*)d_in[3];
    const float* bout     = (const float*)d_in[4];
    const float* Wgate    = (const float*)d_in[5];
    const float* bgate    = (const float*)d_in[6];
    const float* pos_bias = (const float*)d_in[7];
    float* out = (float*)d_out;

    float *qkv, *gate;
    __nv_bfloat16 *xh, *xl, *wqh, *wql, *wgh, *wgl, *woh, *wol, *a2h, *a2l;
    cudaGetSymbolAddress((void**)&qkv,  g_qkv);
    cudaGetSymbolAddress((void**)&gate, g_gate);
    cudaGetSymbolAddress((void**)&xh,  g_xh);  cudaGetSymbolAddress((void**)&xl,  g_xl);
    cudaGetSymbolAddress((void**)&wqh, g_wqh); cudaGetSymbolAddress((void**)&wql, g_wql);
    cudaGetSymbolAddress((void**)&wgh, g_wgh); cudaGetSymbolAddress((void**)&wgl, g_wgl);
    cudaGetSymbolAddress((void**)&woh, g_woh); cudaGetSymbolAddress((void**)&wol, g_wol);
    cudaGetSymbolAddress((void**)&a2h, g_a2h); cudaGetSymbolAddress((void**)&a2l, g_a2l);

    const int SMEM_BYTES = 128 + 2 * 32768;   // pad + 2 stages x (A 16K + B 16K)
    cudaFuncSetAttribute(hmma_gemm<0>, cudaFuncAttributeMaxDynamicSharedMemorySize, SMEM_BYTES);
    cudaFuncSetAttribute(hmma_gemm<1>, cudaFuncAttributeMaxDynamicSharedMemorySize, SMEM_BYTES);

    // 1) fp32 -> bf16 hi/lo splits
    {
        int n4;
        n4 = TOK * D / 4;
        split_kernel<<<(n4 + 255) / 256, 256>>>((const float4*)x, (uint2*)xh, (uint2*)xl, n4);
        n4 = H3 * D / 4;
        split_kernel<<<(n4 + 255) / 256, 256>>>((const float4*)Wqkv, (uint2*)wqh, (uint2*)wql, n4);
        n4 = D * D / 4;
        split_kernel<<<(n4 + 255) / 256, 256>>>((const float4*)Wgate, (uint2*)wgh, (uint2*)wgl, n4);
        split_kernel<<<(n4 + 255) / 256, 256>>>((const float4*)Wout, (uint2*)woh, (uint2*)wol, n4);
    }

    // 2) qkv = x @ Wqkv^T + bqkv            [2048, 3072]
    hmma_gemm<0><<<dim3(H3 / 128, TOK / 128), 256, SMEM_BYTES>>>(xh, xl, wqh, wql, bqkv, qkv, H3, D);
    // 3) gate = sigmoid(x @ Wgate^T + bg)   [2048, 1024]
    hmma_gemm<1><<<dim3(D / 128, TOK / 128), 256, SMEM_BYTES>>>(xh, xl, wgh, wgl, bgate, gate, D, D);
    // 4) attention + gate -> split a2       [2048, 1024]
    attn_kernel<<<(TOK * NH) / 8, 256>>>(qkv, gate, pos_bias, a2h, a2l);
    // 5) out = a2 @ Wout^T + bout           [2048, 1024]
    hmma_gemm<0><<<dim3(D / 128, TOK / 128), 256, SMEM_BYTES>>>(a2h, a2l, woh, wol, bout, out, D, D);
}